// round 16
// baseline (speedup 1.0000x reference)
#include <cuda_runtime.h>
#include <cstdint>

#define BB   128          // batch
#define TT   1024         // time steps
#define INF  64           // input features
#define HH   256          // hidden (both layers)
#define OUTF 64           // output features
#define NCTA 128
#define NTHR 384
#define K0   (INF + HH)   // 320
#define K1   (2 * HH)     // 512

typedef unsigned long long ull;

// Persistent device state (static allocs allowed; no cudaMalloc anywhere)
__device__ __align__(16) float g_XT[TT * INF * BB];   // input transposed [t][i][b]
__device__ __align__(16) float g_h0[2 * HH * BB];     // layer0 h double-buffered [p][k][b]
__device__ __align__(16) float g_h1[2 * HH * BB];     // layer1 h double-buffered
__device__ __align__(16) float g_H1[TT * HH * BB];    // all layer1 h (deferred projection)
__device__ unsigned g_arrive = 0;                     // single barrier counter (reset per launch)

__device__ __forceinline__ float sigf(float x) { return 1.0f / (1.0f + __expf(-x)); }

// PROVEN round-15 barrier: reset-prelude zeroes g_arrive each launch; arrival is
// fire-and-forget red.global.add; all CTAs poll the counter (volatile form).
__device__ __forceinline__ void grid_bar(unsigned& barn)
{
    __syncthreads();
    if (threadIdx.x == 0) {
        __threadfence();
        barn++;
        asm volatile("red.global.add.u32 [%0], 1;" :: "l"(&g_arrive) : "memory");
        const unsigned need = barn * (unsigned)NCTA;
        while ((int)(*(volatile unsigned*)&g_arrive - need) < 0) { }
        __threadfence();
    }
    __syncthreads();
}

// packed dual fp32 FMA: acc(lo,hi) += a(lo,hi) * b(lo,hi)
__device__ __forceinline__ void fma2(ull& acc, ull a, ull b)
{
    asm("fma.rn.f32x2 %0, %1, %2, %0;" : "+l"(acc) : "l"(a), "l"(b));
}
// splat float into both halves of a 64-bit pair (ALU pipe)
__device__ __forceinline__ ull pk(float x)
{
    ull r; asm("mov.b64 %0, {%1, %1};" : "=l"(r) : "f"(x)); return r;
}

// Round-16 GEMM: row-paired FFMA2 with DEPTH-8 register prefetch (2 full groups
// ~290+ cycles of cover vs depth-4's ~128 — hides L2-far). Requires
// (ke-ks) % 8 == 0 and >= 8 (all call sites satisfy this).
// CA=true uses __ldca for h0 (re-read within the tick; L1 flushed at barriers).
template <bool CA>
__device__ __forceinline__ void gemm_seg(ull* acc,
                                         const ulonglong2* __restrict__ ws,
                                         int ks, int ke,
                                         const float* __restrict__ act, int koff, int lane)
{
    const char* ap = (const char*)act + (size_t)(ks - koff) * (BB * 4) + lane * 16;
    const char* pe = (const char*)act + (size_t)(ke - koff) * (BB * 4) + lane * 16;
    float4 buf[8];
#pragma unroll
    for (int j = 0; j < 8; j++) {
        const float4* p = reinterpret_cast<const float4*>(ap + j * (BB * 4));
        buf[j] = CA ? __ldca(p) : __ldcg(p);
    }
    const char* pf = ap + 8 * (BB * 4);
    const ulonglong2* wp = ws + (size_t)ks * 2;

    for (int k = ks; k < ke; k += 8) {
#pragma unroll
        for (int j = 0; j < 8; j++) {
            const float4 a = buf[j];
            if (pf < pe) {
                const float4* p = reinterpret_cast<const float4*>(pf);
                buf[j] = CA ? __ldca(p) : __ldcg(p);
            }
            pf += BB * 4;
            const ull s0 = pk(a.x), s1 = pk(a.y), s2 = pk(a.z), s3 = pk(a.w);
            const ulonglong2 wlo = wp[0];        // row-pairs (r0,r1), (r2,r3)
            const ulonglong2 whi = wp[1];        // row-pairs (r4,r5), (r6,r7)
            wp += 2;
            fma2(acc[0],  wlo.x, s0); fma2(acc[1],  wlo.x, s1);
            fma2(acc[2],  wlo.x, s2); fma2(acc[3],  wlo.x, s3);
            fma2(acc[4],  wlo.y, s0); fma2(acc[5],  wlo.y, s1);
            fma2(acc[6],  wlo.y, s2); fma2(acc[7],  wlo.y, s3);
            fma2(acc[8],  whi.x, s0); fma2(acc[9],  whi.x, s1);
            fma2(acc[10], whi.x, s2); fma2(acc[11], whi.x, s3);
            fma2(acc[12], whi.y, s0); fma2(acc[13], whi.y, s1);
            fma2(acc[14], whi.y, s2); fma2(acc[15], whi.y, s3);
        }
    }
}

// SMEM layout (floats):
#define OFS_WS0 0                      // [K0][8]   layer0 weights (rows = gate*2+unit)
#define OFS_WS1 2560                   // [K1][8]   layer1 weights
#define OFS_P0  6656                   // [4 slot][4 g][128 c][2 u] layer0 partials
#define OFS_P1  10752                  // [8 slot][4 g][128 c][2 u] layer1 partials
#define OFS_CST 18944                  // [2 l][2 u][128 c] cell state
#define OFS_BIA 19456                  // [2 l][8 r] biases
#define SM_FLOATS 19472                // >= 16448 needed by projection phase
#define SM_BYTES  (SM_FLOATS * 4)

// Reset prelude: zero the barrier counter before each main-kernel run.
extern "C" __global__ void barrier_reset_kernel()
{
    g_arrive = 0;
}

extern "C" __global__ void __launch_bounds__(NTHR, 1)
lstm_persistent_kernel(const float* __restrict__ input,
                       const float* __restrict__ W_ih0, const float* __restrict__ W_hh0,
                       const float* __restrict__ b_ih0, const float* __restrict__ b_hh0,
                       const float* __restrict__ W_ih1, const float* __restrict__ W_hh1,
                       const float* __restrict__ b_ih1, const float* __restrict__ b_hh1,
                       const float* __restrict__ W_lin, const float* __restrict__ b_lin,
                       float* __restrict__ out)
{
    extern __shared__ float sm[];
    const int cta  = blockIdx.x;
    const int tid  = threadIdx.x;
    const int w    = tid >> 5;         // 0..3 layer0 k-quarters, 4..11 layer1 k-eighths
    const int lane = tid & 31;

    unsigned barn = 0;

    // ---- Phase 0: init state, stage weights, transpose input ----
    for (int i = tid; i < 512; i += NTHR) sm[OFS_CST + i] = 0.f;
    for (int i = cta * NTHR + tid; i < 2 * HH * BB; i += NCTA * NTHR) {
        g_h0[i] = 0.f;
        g_h1[i] = 0.f;
    }
    // ws0[k*8 + r] = W0[(r>>1)*HH + 2*cta + (r&1)][k], k<INF from W_ih0 else W_hh0
    for (int i = tid; i < K0 * 8; i += NTHR) {
        int k = i >> 3, r = i & 7;
        int row = (r >> 1) * HH + 2 * cta + (r & 1);
        sm[OFS_WS0 + i] = (k < INF) ? W_ih0[row * INF + k] : W_hh0[row * HH + (k - INF)];
    }
    for (int i = tid; i < K1 * 8; i += NTHR) {
        int k = i >> 3, r = i & 7;
        int row = (r >> 1) * HH + 2 * cta + (r & 1);
        sm[OFS_WS1 + i] = (k < HH) ? W_ih1[row * HH + k] : W_hh1[row * HH + (k - HH)];
    }
    if (tid < 16) {
        int l = tid >> 3, r = tid & 7;
        int row = (r >> 1) * HH + 2 * cta + (r & 1);
        sm[OFS_BIA + tid] = l ? (b_ih1[row] + b_hh1[row]) : (b_ih0[row] + b_hh0[row]);
    }
    // transpose this CTA's 8 timesteps: XT[t][i][b] = input[b][t][i]
    for (int t = cta * 8; t < cta * 8 + 8; t++) {
        for (int i = tid; i < INF * BB; i += NTHR) {
            int ii = i >> 7, b = i & 127;
            g_XT[t * INF * BB + ii * BB + b] = input[(size_t)b * TT * INF + t * INF + ii];
        }
    }
    grid_bar(barn);

    const ulonglong2* ws = reinterpret_cast<const ulonglong2*>(sm + ((w < 4) ? OFS_WS0 : OFS_WS1));
    float* pbase = sm + ((w < 4) ? (OFS_P0 + w * 1024) : (OFS_P1 + (w - 4) * 1024));

    // ---- Main loop: tick tau = layer0(tau) + layer1(tau-1); one barrier/tick ----
    for (int tau = 0; tau <= TT; tau++) {
        const int pw = tau & 1;
        const int pr = pw ^ 1;

        ull acc[16];
#pragma unroll
        for (int r = 0; r < 16; r++) acc[r] = 0ull;

        bool did = false;
        if (w < 4) {
            if (tau < TT) {
                did = true;
                const int ks = w * 80, ke = ks + 80;     // 4 x 80 = K0
                if (ks < INF)   // x segment (stream, L2): warp0 k 0..64
                    gemm_seg<false>(acc, ws, ks, min(ke, INF),
                                    g_XT + tau * INF * BB, 0, lane);
                if (ke > INF)   // h0(tau-1) segment (reused -> L1-cached)
                    gemm_seg<true>(acc, ws, max(ks, INF), ke,
                                   g_h0 + pr * HH * BB, INF, lane);
            }
        } else {
            if (tau >= 1) {
                did = true;
                const int kq = w - 4;
                const int ks = kq * 64, ke = ks + 64;    // 8 x 64 = K1
                if (kq < 4)     // h0(tau-1) half (reused -> L1-cached)
                    gemm_seg<true>(acc, ws, ks, ke, g_h0 + pr * HH * BB, 0, lane);
                else            // h1(tau-2) half (stream, L2)
                    gemm_seg<false>(acc, ws, ks, ke, g_h1 + pw * HH * BB, HH, lane);
            }
        }
        if (did) {
            // partial layout per warp slot: ull pp[4 g][128 c], pp[g][c] = (unit0, unit1)
            ull* pp = reinterpret_cast<ull*>(pbase);
#pragma unroll
            for (int rp = 0; rp < 4; rp++) {
                ulonglong2 v01; v01.x = acc[rp * 4 + 0]; v01.y = acc[rp * 4 + 1];
                ulonglong2 v23; v23.x = acc[rp * 4 + 2]; v23.y = acc[rp * 4 + 3];
                *reinterpret_cast<ulonglong2*>(pp + rp * 128 + 4 * lane)     = v01;
                *reinterpret_cast<ulonglong2*>(pp + rp * 128 + 4 * lane + 2) = v23;
            }
        }
        __syncthreads();

        // elementwise: 512 (layer, unit, col) scalars over 384 threads (2 iters for tid<128)
        for (int item = tid; item < 512; item += NTHR) {
            const int el = item >> 8;
            const int eu = (item >> 7) & 1;
            const int ec = item & 127;
            const bool doit = (el == 0) ? (tau < TT) : (tau >= 1);
            if (doit) {
                const float* pb = sm + (el ? OFS_P1 : OFS_P0);
                const int roff0 = 0 * 256 + ec * 2 + eu;
                const int roff1 = 1 * 256 + ec * 2 + eu;
                const int roff2 = 2 * 256 + ec * 2 + eu;
                const int roff3 = 3 * 256 + ec * 2 + eu;
                float g0, g1, g2, g3;
                if (el == 0) {          // 4 partial slots
                    g0 = pb[roff0]; g1 = pb[roff1]; g2 = pb[roff2]; g3 = pb[roff3];
#pragma unroll
                    for (int q = 1; q < 4; q++) {
                        g0 += pb[q * 1024 + roff0]; g1 += pb[q * 1024 + roff1];
                        g2 += pb[q * 1024 + roff2]; g3 += pb[q * 1024 + roff3];
                    }
                } else {                // 8 partial slots
                    g0 = pb[roff0]; g1 = pb[roff1]; g2 = pb[roff2]; g3 = pb[roff3];
#pragma unroll
                    for (int q = 1; q < 8; q++) {
                        g0 += pb[q * 1024 + roff0]; g1 += pb[q * 1024 + roff1];
                        g2 += pb[q * 1024 + roff2]; g3 += pb[q * 1024 + roff3];
                    }
                }
                g0 += sm[OFS_BIA + el * 8 + 0 * 2 + eu];
                g1 += sm[OFS_BIA + el * 8 + 1 * 2 + eu];
                g2 += sm[OFS_BIA + el * 8 + 2 * 2 + eu];
                g3 += sm[OFS_BIA + el * 8 + 3 * 2 + eu];
                const int coff = OFS_CST + (el * 2 + eu) * 128 + ec;
                const float c_old = sm[coff];
                const float cn = sigf(g1) * c_old + sigf(g0) * tanhf(g2);
                sm[coff] = cn;
                const float hn = sigf(g3) * tanhf(cn);
                const int row = 2 * cta + eu;
                if (el == 0) {
                    __stcg(&g_h0[pw * HH * BB + row * BB + ec], hn);
                } else {
                    __stcg(&g_h1[pr * HH * BB + row * BB + ec], hn);
                    __stcg(&g_H1[(size_t)(tau - 1) * HH * BB + row * BB + ec], hn);
                }
            }
        }
        grid_bar(barn);
    }

    // ---- Deferred projection: out[b][t][o] = h1(t) . W_lin[o] + b_lin[o] ----
    for (int i = tid; i < OUTF * HH; i += NTHR) sm[i] = W_lin[i];
    if (tid < OUTF) sm[OUTF * HH + tid] = b_lin[tid];
    __syncthreads();

    // warps 0..7: warp w handles timestep cta*8 + w, all 64 outputs
    if (w < 8) {
        const int t = cta * 8 + w;
        const int bb4 = lane * 4;
        const float* hb = g_H1 + (size_t)t * HH * BB;
        for (int ob = 0; ob < OUTF; ob += 8) {
            float acc[8][4];
#pragma unroll
            for (int oo = 0; oo < 8; oo++) { acc[oo][0] = acc[oo][1] = acc[oo][2] = acc[oo][3] = 0.f; }
            for (int j = 0; j < HH; j++) {
                const float4 hv = *reinterpret_cast<const float4*>(hb + j * BB + bb4);
#pragma unroll
                for (int oo = 0; oo < 8; oo++) {
                    const float wv = sm[(ob + oo) * HH + j];
                    acc[oo][0] += wv * hv.x; acc[oo][1] += wv * hv.y;
                    acc[oo][2] += wv * hv.z; acc[oo][3] += wv * hv.w;
                }
            }
#pragma unroll
            for (int oo = 0; oo < 8; oo++) {
                const int o = ob + oo;
                const float bl = sm[OUTF * HH + o];
                out[(size_t)(bb4 + 0) * TT * OUTF + t * OUTF + o] = acc[oo][0] + bl;
                out[(size_t)(bb4 + 1) * TT * OUTF + t * OUTF + o] = acc[oo][1] + bl;
                out[(size_t)(bb4 + 2) * TT * OUTF + t * OUTF + o] = acc[oo][2] + bl;
                out[(size_t)(bb4 + 3) * TT * OUTF + t * OUTF + o] = acc[oo][3] + bl;
            }
        }
    }
}

extern "C" void kernel_launch(void* const* d_in, const int* in_sizes, int n_in,
                              void* d_out, int out_size)
{
    (void)in_sizes; (void)n_in; (void)out_size;
    cudaFuncSetAttribute(lstm_persistent_kernel,
                         cudaFuncAttributeMaxDynamicSharedMemorySize, SM_BYTES);
    barrier_reset_kernel<<<1, 1>>>();
    lstm_persistent_kernel<<<NCTA, NTHR, SM_BYTES>>>(
        (const float*)d_in[0],
        (const float*)d_in[1], (const float*)d_in[2],
        (const float*)d_in[3], (const float*)d_in[4],
        (const float*)d_in[5], (const float*)d_in[6],
        (const float*)d_in[7], (const float*)d_in[8],
        (const float*)d_in[9], (const float*)d_in[10],
        (float*)d_out);
}

// round 17
// speedup vs baseline: 1.2104x; 1.2104x over previous
#include <cuda_runtime.h>
#include <cstdint>

#define BB   128          // batch
#define TT   1024         // time steps
#define INF  64           // input features
#define HH   256          // hidden (both layers)
#define OUTF 64           // output features
#define NCTA 128
#define NTHR 512
#define K0   (INF + HH)   // 320
#define K1   (2 * HH)     // 512

typedef unsigned long long ull;

// Persistent device state (static allocs allowed; no cudaMalloc anywhere)
__device__ __align__(16) float g_XT[TT * INF * BB];   // input transposed [t][i][b]
__device__ __align__(16) float g_h0[2 * HH * BB];     // layer0 h double-buffered [p][k][b]
__device__ __align__(16) float g_h1[2 * HH * BB];     // layer1 h double-buffered
__device__ __align__(16) float g_H1[TT * HH * BB];    // all layer1 h (deferred projection)
__device__ unsigned g_arrive = 0;                     // single barrier counter (reset per launch)

__device__ __forceinline__ float sigf(float x) { return 1.0f / (1.0f + __expf(-x)); }

// Fast tanh (round-17): clamp + exp identity. ~5 instrs vs libm's ~20+ polynomial.
// rel err ~1e-6 (MUFU.EX2 + approx divide); clamp avoids inf/inf NaN for |x|>44.
__device__ __forceinline__ float ftanh(float x)
{
    x = fminf(15.0f, fmaxf(-15.0f, x));
    const float e = __expf(2.0f * x);
    return __fdividef(e - 1.0f, e + 1.0f);
}

// PROVEN round-15 barrier: reset-prelude zeroes g_arrive each launch; arrival is
// fire-and-forget red.global.add; all CTAs poll the counter (volatile form).
__device__ __forceinline__ void grid_bar(unsigned& barn)
{
    __syncthreads();
    if (threadIdx.x == 0) {
        __threadfence();
        barn++;
        asm volatile("red.global.add.u32 [%0], 1;" :: "l"(&g_arrive) : "memory");
        const unsigned need = barn * (unsigned)NCTA;
        while ((int)(*(volatile unsigned*)&g_arrive - need) < 0) { }
        __threadfence();
    }
    __syncthreads();
}

// packed dual fp32 FMA: acc(lo,hi) += a(lo,hi) * b(lo,hi)
__device__ __forceinline__ void fma2(ull& acc, ull a, ull b)
{
    asm("fma.rn.f32x2 %0, %1, %2, %0;" : "+l"(acc) : "l"(a), "l"(b));
}
// splat float into both halves of a 64-bit pair (ALU pipe)
__device__ __forceinline__ ull pk(float x)
{
    ull r; asm("mov.b64 %0, {%1, %1};" : "=l"(r) : "f"(x)); return r;
}

// The 16-FFMA2 core for one k-iter: row-paired weights from SMEM, 4 splatted cols.
#define FFMA2_BLOCK(a, wlo, whi)                                        \
    do {                                                                \
        const ull s0 = pk((a).x), s1 = pk((a).y),                       \
                  s2 = pk((a).z), s3 = pk((a).w);                       \
        fma2(acc[0],  (wlo).x, s0); fma2(acc[1],  (wlo).x, s1);         \
        fma2(acc[2],  (wlo).x, s2); fma2(acc[3],  (wlo).x, s3);         \
        fma2(acc[4],  (wlo).y, s0); fma2(acc[5],  (wlo).y, s1);         \
        fma2(acc[6],  (wlo).y, s2); fma2(acc[7],  (wlo).y, s3);         \
        fma2(acc[8],  (whi).x, s0); fma2(acc[9],  (whi).x, s1);         \
        fma2(acc[10], (whi).x, s2); fma2(acc[11], (whi).x, s3);         \
        fma2(acc[12], (whi).y, s0); fma2(acc[13], (whi).y, s1);         \
        fma2(acc[14], (whi).y, s2); fma2(acc[15], (whi).y, s3);         \
    } while (0)

// Round-17 GEMM: group-peeled prefetch — main loop over ng-1 groups prefetches
// the next group UNCONDITIONALLY with immediate-offset loads from one base
// pointer (no per-load ISETP, one pointer add per group); the peeled last group
// only consumes. Same loads/math/registers as R15, ~6 fewer instrs per 4 k.
// Requires (ke-ks) % 4 == 0 and >= 8 (all call sites satisfy: 16..64).
// CA=true -> __ldca (h0: re-read within tick, L1 flushed at each barrier).
template <bool CA>
__device__ __forceinline__ void gemm_seg(ull* acc,
                                         const ulonglong2* __restrict__ ws,
                                         int ks, int ke,
                                         const float* __restrict__ act, int koff, int lane)
{
    const char* p = (const char*)act + (size_t)(ks - koff) * (BB * 4) + lane * 16;
    const ulonglong2* wp = ws + (size_t)ks * 2;
    float4 buf[4];
#pragma unroll
    for (int j = 0; j < 4; j++) {
        const float4* q = reinterpret_cast<const float4*>(p + j * (BB * 4));
        buf[j] = CA ? __ldca(q) : __ldcg(q);
    }
    p += 4 * (BB * 4);

    const int ng = (ke - ks) >> 2;
    for (int g = 0; g < ng - 1; g++) {
#pragma unroll
        for (int j = 0; j < 4; j++) {
            const float4 a = buf[j];
            const float4* q = reinterpret_cast<const float4*>(p + j * (BB * 4));
            buf[j] = CA ? __ldca(q) : __ldcg(q);
            const ulonglong2 wlo = wp[2 * j];
            const ulonglong2 whi = wp[2 * j + 1];
            FFMA2_BLOCK(a, wlo, whi);
        }
        p += 4 * (BB * 4);
        wp += 8;
    }
    // peeled final group: consume only
#pragma unroll
    for (int j = 0; j < 4; j++) {
        const float4 a = buf[j];
        const ulonglong2 wlo = wp[2 * j];
        const ulonglong2 whi = wp[2 * j + 1];
        FFMA2_BLOCK(a, wlo, whi);
    }
}

// SMEM layout (floats):
#define OFS_WS0 0                      // [K0][8]   layer0 weights (rows = gate*2+unit)
#define OFS_WS1 2560                   // [K1][8]   layer1 weights
#define OFS_P0  6656                   // [8 kq][4 g][128 c][2 u] layer0 partials
#define OFS_P1  14848                  // [8 kq][4 g][128 c][2 u] layer1 partials
#define OFS_CST 23040                  // [2 l][2 u][128 c] cell state
#define OFS_BIA 23552                  // [2 l][8 r] biases
#define SM_FLOATS 23568                // >= 16448 needed by projection phase
#define SM_BYTES  (SM_FLOATS * 4)

// Reset prelude: zero the barrier counter before each main-kernel run.
extern "C" __global__ void barrier_reset_kernel()
{
    g_arrive = 0;
}

extern "C" __global__ void __launch_bounds__(NTHR, 1)
lstm_persistent_kernel(const float* __restrict__ input,
                       const float* __restrict__ W_ih0, const float* __restrict__ W_hh0,
                       const float* __restrict__ b_ih0, const float* __restrict__ b_hh0,
                       const float* __restrict__ W_ih1, const float* __restrict__ W_hh1,
                       const float* __restrict__ b_ih1, const float* __restrict__ b_hh1,
                       const float* __restrict__ W_lin, const float* __restrict__ b_lin,
                       float* __restrict__ out)
{
    extern __shared__ float sm[];
    const int cta  = blockIdx.x;
    const int tid  = threadIdx.x;
    const int w    = tid >> 5;         // 0..7 layer0 k-eighths, 8..15 layer1 k-eighths
    const int lane = tid & 31;

    unsigned barn = 0;

    // ---- Phase 0: init state, stage weights, transpose input ----
    for (int i = tid; i < 512; i += NTHR) sm[OFS_CST + i] = 0.f;
    for (int i = cta * NTHR + tid; i < 2 * HH * BB; i += NCTA * NTHR) {
        g_h0[i] = 0.f;
        g_h1[i] = 0.f;
    }
    // ws0[k*8 + r] = W0[(r>>1)*HH + 2*cta + (r&1)][k], k<INF from W_ih0 else W_hh0
    for (int i = tid; i < K0 * 8; i += NTHR) {
        int k = i >> 3, r = i & 7;
        int row = (r >> 1) * HH + 2 * cta + (r & 1);
        sm[OFS_WS0 + i] = (k < INF) ? W_ih0[row * INF + k] : W_hh0[row * HH + (k - INF)];
    }
    for (int i = tid; i < K1 * 8; i += NTHR) {
        int k = i >> 3, r = i & 7;
        int row = (r >> 1) * HH + 2 * cta + (r & 1);
        sm[OFS_WS1 + i] = (k < HH) ? W_ih1[row * HH + k] : W_hh1[row * HH + (k - HH)];
    }
    if (tid < 16) {
        int l = tid >> 3, r = tid & 7;
        int row = (r >> 1) * HH + 2 * cta + (r & 1);
        sm[OFS_BIA + tid] = l ? (b_ih1[row] + b_hh1[row]) : (b_ih0[row] + b_hh0[row]);
    }
    // transpose this CTA's 8 timesteps: XT[t][i][b] = input[b][t][i]
    for (int t = cta * 8; t < cta * 8 + 8; t++) {
        for (int i = tid; i < INF * BB; i += NTHR) {
            int ii = i >> 7, b = i & 127;
            g_XT[t * INF * BB + ii * BB + b] = input[(size_t)b * TT * INF + t * INF + ii];
        }
    }
    grid_bar(barn);

    const ulonglong2* ws = reinterpret_cast<const ulonglong2*>(sm + ((w < 8) ? OFS_WS0 : OFS_WS1));
    float* pbase = sm + ((w < 8) ? OFS_P0 : OFS_P1) + (w & 7) * 1024;  // [g][c][u]

    // ew role (all 512 threads, 1 scalar item each): layer el, unit eu, col ec
    const int el = tid >> 8;
    const int eu = (tid >> 7) & 1;
    const int ec = tid & 127;

    // ---- Main loop: tick tau = layer0(tau) + layer1(tau-1); one barrier/tick ----
    for (int tau = 0; tau <= TT; tau++) {
        const int pw = tau & 1;
        const int pr = pw ^ 1;

        ull acc[16];
#pragma unroll
        for (int r = 0; r < 16; r++) acc[r] = 0ull;

        bool did = false;
        if (w < 8) {
            if (tau < TT) {
                did = true;
                const int ks = w * 40, ke = ks + 40;     // 8 x 40 = K0
                if (ks < INF)   // x segment (stream, L2)
                    gemm_seg<false>(acc, ws, ks, min(ke, INF),
                                    g_XT + tau * INF * BB, 0, lane);
                if (ke > INF)   // h0(tau-1) segment (reused -> L1-cached)
                    gemm_seg<true>(acc, ws, max(ks, INF), ke,
                                   g_h0 + pr * HH * BB, INF, lane);
            }
        } else {
            if (tau >= 1) {
                did = true;
                const int kq = w - 8;
                const int ks = kq * 64, ke = ks + 64;    // 8 x 64 = K1
                if (kq < 4)     // h0(tau-1) half (reused -> L1-cached)
                    gemm_seg<true>(acc, ws, ks, ke, g_h0 + pr * HH * BB, 0, lane);
                else            // h1(tau-2) half (stream, L2)
                    gemm_seg<false>(acc, ws, ks, ke, g_h1 + pw * HH * BB, HH, lane);
            }
        }
        if (did) {
            // partial layout per warp: ull pp[4 g][128 c], pp[g][c] = (unit0, unit1)
            ull* pp = reinterpret_cast<ull*>(pbase);
#pragma unroll
            for (int rp = 0; rp < 4; rp++) {
                ulonglong2 v01; v01.x = acc[rp * 4 + 0]; v01.y = acc[rp * 4 + 1];
                ulonglong2 v23; v23.x = acc[rp * 4 + 2]; v23.y = acc[rp * 4 + 3];
                *reinterpret_cast<ulonglong2*>(pp + rp * 128 + 4 * lane)     = v01;
                *reinterpret_cast<ulonglong2*>(pp + rp * 128 + 4 * lane + 2) = v23;
            }
        }
        __syncthreads();

        // elementwise: each thread owns ONE (layer, unit, col) scalar
        {
            const bool doit = (el == 0) ? (tau < TT) : (tau >= 1);
            if (doit) {
                const float* pb = sm + (el ? OFS_P1 : OFS_P0);
                float gv[4];
#pragma unroll
                for (int g = 0; g < 4; g++) {
                    const int roff = g * 256 + ec * 2 + eu;   // [g][c][u]
                    float s = pb[roff];
#pragma unroll
                    for (int q = 1; q < 8; q++) s += pb[q * 1024 + roff];
                    gv[g] = s + sm[OFS_BIA + el * 8 + g * 2 + eu];
                }
                const int coff = OFS_CST + (el * 2 + eu) * 128 + ec;
                const float c_old = sm[coff];
                const float cn = sigf(gv[1]) * c_old + sigf(gv[0]) * ftanh(gv[2]);
                sm[coff] = cn;
                const float hn = sigf(gv[3]) * ftanh(cn);
                const int row = 2 * cta + eu;
                if (el == 0) {
                    __stcg(&g_h0[pw * HH * BB + row * BB + ec], hn);
                } else {
                    __stcg(&g_h1[pr * HH * BB + row * BB + ec], hn);
                    __stcg(&g_H1[(size_t)(tau - 1) * HH * BB + row * BB + ec], hn);
                }
            }
        }
        grid_bar(barn);
    }

    // ---- Deferred projection: out[b][t][o] = h1(t) . W_lin[o] + b_lin[o] ----
    for (int i = tid; i < OUTF * HH; i += NTHR) sm[i] = W_lin[i];
    if (tid < OUTF) sm[OUTF * HH + tid] = b_lin[tid];
    __syncthreads();

    // 16 warps: warp w handles timestep cta*8 + (w&7), output block (w>>3)*32..+32
    const int t = cta * 8 + (w & 7);
    const int obase = (w >> 3) * 32;
    const int bb4 = lane * 4;
    const float* hb = g_H1 + (size_t)t * HH * BB;
    for (int ob = obase; ob < obase + 32; ob += 8) {
        float acc[8][4];
#pragma unroll
        for (int oo = 0; oo < 8; oo++) { acc[oo][0] = acc[oo][1] = acc[oo][2] = acc[oo][3] = 0.f; }
        for (int j = 0; j < HH; j++) {
            const float4 hv = *reinterpret_cast<const float4*>(hb + j * BB + bb4);
#pragma unroll
            for (int oo = 0; oo < 8; oo++) {
                const float wv = sm[(ob + oo) * HH + j];
                acc[oo][0] += wv * hv.x; acc[oo][1] += wv * hv.y;
                acc[oo][2] += wv * hv.z; acc[oo][3] += wv * hv.w;
            }
        }
#pragma unroll
        for (int oo = 0; oo < 8; oo++) {
            const int o = ob + oo;
            const float bl = sm[OUTF * HH + o];
            out[(size_t)(bb4 + 0) * TT * OUTF + t * OUTF + o] = acc[oo][0] + bl;
            out[(size_t)(bb4 + 1) * TT * OUTF + t * OUTF + o] = acc[oo][1] + bl;
            out[(size_t)(bb4 + 2) * TT * OUTF + t * OUTF + o] = acc[oo][2] + bl;
            out[(size_t)(bb4 + 3) * TT * OUTF + t * OUTF + o] = acc[oo][3] + bl;
        }
    }
}

extern "C" void kernel_launch(void* const* d_in, const int* in_sizes, int n_in,
                              void* d_out, int out_size)
{
    (void)in_sizes; (void)n_in; (void)out_size;
    cudaFuncSetAttribute(lstm_persistent_kernel,
                         cudaFuncAttributeMaxDynamicSharedMemorySize, SM_BYTES);
    barrier_reset_kernel<<<1, 1>>>();
    lstm_persistent_kernel<<<NCTA, NTHR, SM_BYTES>>>(
        (const float*)d_in[0],
        (const float*)d_in[1], (const float*)d_in[2],
        (const float*)d_in[3], (const float*)d_in[4],
        (const float*)d_in[5], (const float*)d_in[6],
        (const float*)d_in[7], (const float*)d_in[8],
        (const float*)d_in[9], (const float*)d_in[10],
        (float*)d_out);
}